// round 17
// baseline (speedup 1.0000x reference)
#include <cuda_runtime.h>
#include <cuda_fp16.h>
#include <cstdint>

// ---------------------------------------------------------------------------
// Problem constants
// ---------------------------------------------------------------------------
#define BATCH   32768
#define XROW    3072      // x row stride (3*32*32)
#define EMBED   16
#define TINY    16
#define NEXP    4
#define OUTD    1000

#define THREADS 512       // 16 warps, 256 rows per CTA, 1 CTA/SM

// ---------------------------------------------------------------------------
// K-permutation note: within every 16-wide MMA K-chunk, fragment ks
// {2t,2t+1,2t+8,2t+9} (lane tig=t) are mapped to physical ks {4t..4t+3}.
// Applied consistently to A and B on both GEMMs, so results are identical
// (fp32 accumulation order within one HMMA group is HW-defined anyway).
// Consequence: A frag = one float4 LDS; B frag pair = one uint2 LDS; and the
// phase-2 Wc conversion layout is unchanged (natural half2 pair order).
// ---------------------------------------------------------------------------

// ---------------------------------------------------------------------------
// smem layout (float offsets).  Total 55572 floats = 222288 B -> 1 CTA/SM.
//
// Phase 1:
//   [0     , 8320 )  Ws: W_embed fp16 [16][1040]  (row stride 520 words)
//   [8320  , 54400)  ring: 16 warps x 2880 floats (5 slots x [16][36] fp32)
//                    per-warp scratch overlays ring at +768 after mainloop:
//                    es[16][20] then As_w[16][80]  (warp0 scratch >= 9088)
//   [54400 , 55572)  small weights (W1, Wg, b1, be, bg)
// Phase 2 overlay (after phase-1 consumers are done):
//   [0     , 8976 )  stage: raw fp32 Wc chunk [68][132]   (< warp0 scratch)
//   [8976  , 14608)  Wc: fp16 [128 n][88 k]  (half2 word index = 44*n + kp)
// ---------------------------------------------------------------------------
#define OFF_WS     0
#define WS_WSTRIDE 520       // unsigned words per Ws row (1040 halfs)
#define OFF_RING   8320
#define RING_D     5
#define RW_FLOATS  2880      // per-warp ring floats (5 slots)
#define SLOT_F     576       // per slot: 16 rows x 36
#define XS_STRIDE  36
#define SCR_OFF    768       // warp scratch offset inside its ring region
#define AS_STRIDE  80        // As_w row stride (72 data + 8 zero pad)
#define OFF_SW1    54400
#define OFF_SWG    55424
#define OFF_SB1    55488
#define OFF_SBE    55552
#define OFF_SBG    55568
#define SMEM_FLOATS 55572

#define OFF_STAGE  0
#define STG_STRIDE 132
#define OFF_WC     8976      // floats; as unsigned words: word = 44*n + kp

// ---------------------------------------------------------------------------
// Helpers
// ---------------------------------------------------------------------------
__device__ __forceinline__ unsigned pack_h2(float lo, float hi) {
    unsigned r;   // PTX: first source -> high half
    asm("cvt.rn.f16x2.f32 %0, %1, %2;" : "=r"(r) : "f"(hi), "f"(lo));
    return r;
}

__device__ __forceinline__ void ffma2(unsigned long long& acc,
                                      unsigned long long a,
                                      unsigned long long b) {
    asm("fma.rn.f32x2 %0, %1, %2, %0;" : "+l"(acc) : "l"(a), "l"(b));
}

__device__ __forceinline__ void mma_f16(float* c, const unsigned* a,
                                        unsigned b0, unsigned b1) {
    asm volatile(
        "mma.sync.aligned.m16n8k16.row.col.f32.f16.f16.f32 "
        "{%0,%1,%2,%3}, {%4,%5,%6,%7}, {%8,%9}, {%0,%1,%2,%3};"
        : "+f"(c[0]), "+f"(c[1]), "+f"(c[2]), "+f"(c[3])
        : "r"(a[0]), "r"(a[1]), "r"(a[2]), "r"(a[3]), "r"(b0), "r"(b1));
}

__device__ __forceinline__ void cp_async16(float* s, const float* g) {
    unsigned sa = (unsigned)__cvta_generic_to_shared(s);
    asm volatile("cp.async.ca.shared.global [%0], [%1], 16;" :: "r"(sa), "l"(g));
}
#define CP_COMMIT() asm volatile("cp.async.commit_group;")
#define CP_WAIT(n)  asm volatile("cp.async.wait_group %0;" :: "n"(n))

// Stage one raw Wc chunk (rows 0..63 = W2 flat, 64..67 = b2) via cp.async.
// Columns clamped to 996 (garbage loaded in-bounds; zeroed at conversion).
__device__ __forceinline__ void issue_stage(float* sm, const float* W2,
                                            const float* b2, int nb, int tid) {
#pragma unroll
    for (int j = 0; j < 5; j++) {
        int i = tid + j * THREADS;
        if (i < 68 * 33) {
            int r = i / 33, c4 = i % 33;
            int col = nb * 128 + c4 * 4;
            if (col > 996) col = 996;
            const float* src = (r < 64) ? (W2 + r * OUTD + col)
                                        : (b2 + (r - 64) * OUTD + col);
            cp_async16(sm + OFF_STAGE + r * STG_STRIDE + c4 * 4, src);
        }
    }
    CP_COMMIT();
}

// ---------------------------------------------------------------------------
// Fused kernel.  One CTA = 256 batch rows, 512 threads (16 warps), grid 128.
// Each warp owns 16 rows end-to-end: barrier-free phase-1 pipeline, warp-local
// epilogue, A fragments kept in registers for phase 2.
// ---------------------------------------------------------------------------
__global__ void __launch_bounds__(THREADS, 1)
k_fused(const float* __restrict__ x,
        const float* __restrict__ We, const float* __restrict__ be,
        const float* __restrict__ W1, const float* __restrict__ b1,
        const float* __restrict__ W2, const float* __restrict__ b2,
        const float* __restrict__ Wg, const float* __restrict__ bg,
        float* __restrict__ out) {
    extern __shared__ float sm[];
    const int tid  = threadIdx.x;
    const int wid  = tid >> 5, lane = tid & 31;
    const int tig  = lane & 3, grp = lane >> 2;

    float* ringw = sm + OFF_RING + wid * RW_FLOATS;
    const float* xw = x + ((size_t)blockIdx.x * 256 + wid * 16) * XROW;

    // ---- preload x chunks 0..3 into this warp's ring (issued first) ----
#pragma unroll
    for (int s = 0; s < RING_D - 1; s++) {
        float* slot = ringw + s * SLOT_F;
#pragma unroll
        for (int i = 0; i < 4; i++) {
            int idx = lane + 32 * i;
            int r = idx >> 3, c4 = idx & 7;
            cp_async16(slot + r * XS_STRIDE + c4 * 4,
                       xw + (size_t)r * XROW + s * 32 + c4 * 4);
        }
        CP_COMMIT();
    }

    // ---- small weights ----
    for (int i = tid; i < 1024; i += THREADS) sm[OFF_SW1 + i] = W1[i];
    if (tid < 64)       sm[OFF_SWG + tid] = Wg[tid];
    else if (tid < 128) sm[OFF_SB1 + tid - 64] = b1[tid - 64];
    else if (tid < 144) sm[OFF_SBE + tid - 128] = be[tid - 128];
    else if (tid < 148) sm[OFF_SBG + tid - 144] = bg[tid - 144];

    // ---- W_embed -> fp16 smem [16][1040] (natural k order) ----
    {
        unsigned* wsu = (unsigned*)(sm + OFF_WS);
        for (int i = tid; i < 4096; i += THREADS) {
            float4 v = ((const float4*)We)[i];
            int row = i >> 8, c4 = i & 255;
            uint2 p = make_uint2(pack_h2(v.x, v.y), pack_h2(v.z, v.w));
            *(uint2*)&wsu[row * WS_WSTRIDE + c4 * 2] = p;
        }
    }
    __syncthreads();   // Ws + small weights visible

    // ---------------- phase-1 mainloop: barrier-free per warp -------------
    const unsigned* wsu = (const unsigned*)(sm + OFF_WS);
    float c0[4] = {0.f, 0.f, 0.f, 0.f};
    float c1[4] = {0.f, 0.f, 0.f, 0.f};

    int cons = 0, prod = RING_D - 1;       // ring slot cursors (mod 5)
    for (int kc = 0; kc < 32; kc++) {
        CP_WAIT(3);        // this warp's chunk kc has arrived
        __syncwarp();      // cross-lane visibility + ordering before reuse
        if (kc + RING_D - 1 < 32) {        // refill prod slot with chunk kc+4
            float* slot = ringw + prod * SLOT_F;
            const float* src = xw + (size_t)(kc + RING_D - 1) * 32;
#pragma unroll
            for (int i = 0; i < 4; i++) {
                int idx = lane + 32 * i;
                int r = idx >> 3, c4 = idx & 7;
                cp_async16(slot + r * XS_STRIDE + c4 * 4,
                           src + (size_t)r * XROW + c4 * 4);
            }
        }
        CP_COMMIT();       // unconditional: keeps group arithmetic uniform

        const float* xs = ringw + cons * SLOT_F;
#pragma unroll
        for (int s = 0; s < 2; s++) {
            const int k0 = 16 * s + 4 * tig;           // permuted A frag
            float4 q0 = *(const float4*)(xs + grp * XS_STRIDE + k0);
            float4 q1 = *(const float4*)(xs + (grp + 8) * XS_STRIDE + k0);
            unsigned a[4];
            a[0] = pack_h2(q0.x, q0.y);
            a[1] = pack_h2(q1.x, q1.y);
            a[2] = pack_h2(q0.z, q0.w);
            a[3] = pack_h2(q1.z, q1.w);
            const int kw = kc * 16 + 8 * s + 2 * tig;  // permuted B pair
            uint2 b0 = *(const uint2*)&wsu[grp * WS_WSTRIDE + kw];
            uint2 b1 = *(const uint2*)&wsu[(8 + grp) * WS_WSTRIDE + kw];
            mma_f16(c0, a, b0.x, b0.y);
            mma_f16(c1, a, b1.x, b1.y);
        }
        cons = (cons == RING_D - 1) ? 0 : cons + 1;
        prod = (prod == RING_D - 1) ? 0 : prod + 1;
    }
    __syncwarp();          // final slot reads done before scratch overlays ring
    __syncthreads();       // everyone done with Ws region
    issue_stage(sm, W2, b2, 0, tid);   // Wc chunk 0 DMA overlaps epilogue
                                       // (stage [0,8976) < warp0 scratch @9088)

    // ---------------- warp-local epilogue ----------------
    float* es   = ringw + SCR_OFF;          // [16][20]
    float* As_w = ringw + SCR_OFF + 320;    // [16][80]
    {
        int jb = 2 * tig;
        *(float2*)(es + grp * 20 + jb)            = make_float2(c0[0], c0[1]);
        *(float2*)(es + (grp + 8) * 20 + jb)      = make_float2(c0[2], c0[3]);
        *(float2*)(es + grp * 20 + 8 + jb)        = make_float2(c1[0], c1[1]);
        *(float2*)(es + (grp + 8) * 20 + 8 + jb)  = make_float2(c1[2], c1[3]);
    }
    __syncwarp();

    if (lane < 16) {
        const float* sbe = sm + OFF_SBE;
        float e[EMBED];
#pragma unroll
        for (int q = 0; q < 4; q++) {
            float4 v = *(float4*)(es + lane * 20 + q * 4);
            e[q * 4 + 0] = fmaxf(v.x + sbe[q * 4 + 0], 0.f);
            e[q * 4 + 1] = fmaxf(v.y + sbe[q * 4 + 1], 0.f);
            e[q * 4 + 2] = fmaxf(v.z + sbe[q * 4 + 2], 0.f);
            e[q * 4 + 3] = fmaxf(v.w + sbe[q * 4 + 3], 0.f);
        }
        const float* sWg = sm + OFF_SWG;
        const float* sbg = sm + OFF_SBG;
        float g[NEXP];
#pragma unroll
        for (int ex = 0; ex < NEXP; ex++) {
            float s = sbg[ex];
#pragma unroll
            for (int j = 0; j < EMBED; j++) s += e[j] * sWg[ex * EMBED + j];
            g[ex] = s;
        }
        float mx = fmaxf(fmaxf(g[0], g[1]), fmaxf(g[2], g[3]));
        float den = 0.f;
#pragma unroll
        for (int ex = 0; ex < NEXP; ex++) { g[ex] = __expf(g[ex] - mx); den += g[ex]; }
        float inv = 1.0f / den;
#pragma unroll
        for (int ex = 0; ex < NEXP; ex++) g[ex] *= inv;

        float* Arow = As_w + lane * AS_STRIDE;
        const float* sW1 = sm + OFF_SW1;
        const float* sb1 = sm + OFF_SB1;
#pragma unroll
        for (int ex = 0; ex < NEXP; ex++) {
            unsigned long long acc[8];
            const ulonglong2* bp = (const ulonglong2*)(sb1 + ex * TINY);
#pragma unroll
            for (int h = 0; h < 4; h++) {
                ulonglong2 t = bp[h];
                acc[2 * h] = t.x; acc[2 * h + 1] = t.y;
            }
#pragma unroll
            for (int j = 0; j < EMBED; j++) {
                unsigned long long ej2;
                asm("mov.b64 %0, {%1, %1};" : "=l"(ej2) : "f"(e[j]));
                const ulonglong2* wp =
                    (const ulonglong2*)(sW1 + (ex * EMBED + j) * TINY);
#pragma unroll
                for (int h = 0; h < 4; h++) {
                    ulonglong2 w = wp[h];
                    ffma2(acc[2 * h], ej2, w.x);
                    ffma2(acc[2 * h + 1], ej2, w.y);
                }
            }
            float gx = g[ex];
#pragma unroll
            for (int h = 0; h < 8; h++) {
                float lo, hi;
                asm("mov.b64 {%0,%1}, %2;" : "=f"(lo), "=f"(hi) : "l"(acc[h]));
                Arow[ex * TINY + 2 * h]     = fmaxf(lo, 0.f) * gx;
                Arow[ex * TINY + 2 * h + 1] = fmaxf(hi, 0.f) * gx;
            }
        }
        *(float4*)(Arow + 64) = make_float4(g[0], g[1], g[2], g[3]);
        *(float4*)(Arow + 68) = make_float4(0.f, 0.f, 0.f, 0.f);
        *(float4*)(Arow + 72) = make_float4(0.f, 0.f, 0.f, 0.f);
        *(float4*)(Arow + 76) = make_float4(0.f, 0.f, 0.f, 0.f);
    }
    __syncwarp();

    // ---- build A fragments in registers (fp16, permuted, K 72->80 pad) ----
    unsigned af[5][4];
#pragma unroll
    for (int s = 0; s < 5; s++) {
        const int k0 = 16 * s + 4 * tig;
        float4 q0 = *(const float4*)(As_w + grp * AS_STRIDE + k0);
        float4 q1 = *(const float4*)(As_w + (grp + 8) * AS_STRIDE + k0);
        af[s][0] = pack_h2(q0.x, q0.y);
        af[s][1] = pack_h2(q1.x, q1.y);
        af[s][2] = pack_h2(q0.z, q0.w);
        af[s][3] = pack_h2(q1.z, q1.w);
    }

    CP_WAIT(0);        // stage chunk 0 arrived (also drains tail x groups)
    __syncthreads();   // scratch reads done; stage visible; overlays now safe

    // ---------------- phase 2: out = A @ Wc, 8 N-chunks of 128 -------------
    unsigned* wc = (unsigned*)(sm + OFF_WC);
    const int cvt_n  = tid & 127;         // conversion: this thread's n column
    const int cvt_kh = tid >> 7;          // kp quarter (10 kp values each)
    const int gr = blockIdx.x * 256 + wid * 16 + grp;

    for (int nb = 0; nb < 8; nb++) {
        // convert stage (fp32 [k][n]) -> Wc (fp16 [n][k] pairs), zero invalid
        {
            const bool valid = (nb * 128 + cvt_n) < OUTD;
            const float* stg = sm + OFF_STAGE + cvt_n;
#pragma unroll
            for (int q = 0; q < 10; q++) {
                int kp = cvt_kh * 10 + q;
                unsigned v = 0u;
                if (valid && kp < 34)
                    v = pack_h2(stg[(2 * kp) * STG_STRIDE],
                                stg[(2 * kp + 1) * STG_STRIDE]);
                wc[44 * cvt_n + kp] = v;
            }
        }
        __syncthreads();                    // Wc ready; stage drained
        if (nb < 7) issue_stage(sm, W2, b2, nb + 1, tid);  // overlap DMA

        // two N-halves of 64 cols: 32 live accumulators instead of 64
#pragma unroll
        for (int half = 0; half < 2; half++) {
            float cc[8][4];
#pragma unroll
            for (int n8 = 0; n8 < 8; n8++)
#pragma unroll
                for (int q = 0; q < 4; q++) cc[n8][q] = 0.f;

#pragma unroll
            for (int s = 0; s < 5; s++) {
#pragma unroll
                for (int n8 = 0; n8 < 8; n8++) {
                    const int nc = 64 * half + 8 * n8 + grp;
                    uint2 b = *(const uint2*)&wc[44 * nc + 8 * s + 2 * tig];
                    mma_f16(cc[n8], af[s], b.x, b.y);
                }
            }
            // stores: predicated float2 (OUTD even -> pairs all-or-none)
#pragma unroll
            for (int n8 = 0; n8 < 8; n8++) {
                int gc = nb * 128 + 64 * half + 8 * n8 + 2 * tig;
                if (gc < OUTD) {
                    *(float2*)(out + (size_t)gr * OUTD + gc) =
                        make_float2(cc[n8][0], cc[n8][1]);
                    *(float2*)(out + (size_t)(gr + 8) * OUTD + gc) =
                        make_float2(cc[n8][2], cc[n8][3]);
                }
            }
        }

        if (nb < 7) {
            CP_WAIT(0);        // next raw chunk arrived
            __syncthreads();   // all Wc reads done before next conversion
        }
    }
}

// ---------------------------------------------------------------------------
// Launch
// ---------------------------------------------------------------------------
extern "C" void kernel_launch(void* const* d_in, const int* in_sizes, int n_in,
                              void* d_out, int out_size) {
    const float* x   = (const float*)d_in[0];
    const float* We  = (const float*)d_in[1];
    const float* be  = (const float*)d_in[2];
    const float* W1  = (const float*)d_in[3];
    const float* b1  = (const float*)d_in[4];
    const float* W2  = (const float*)d_in[5];
    const float* b2  = (const float*)d_in[6];
    const float* Wg  = (const float*)d_in[7];
    const float* bg  = (const float*)d_in[8];
    float* out = (float*)d_out;

    static bool attr_done = false;  // attribute setting only; deterministic
    if (!attr_done) {
        cudaFuncSetAttribute(k_fused, cudaFuncAttributeMaxDynamicSharedMemorySize,
                             SMEM_FLOATS * 4);
        attr_done = true;
    }

    k_fused<<<BATCH / 256, THREADS, SMEM_FLOATS * 4>>>(x, We, be, W1, b1,
                                                       W2, b2, Wg, bg, out);
}